// round 7
// baseline (speedup 1.0000x reference)
#include <cuda_runtime.h>
#include <cuda_bf16.h>
#include <cstdint>

#define Bv 64
#define Sv 256
#define Hv 768
#define Tv 13
#define Dv 64
#define NQK 1664          /* T*2*D */
#define M1 16384          /* B*S */
#define NEGC 1000000000000.0f

// Scratch (static __device__ to satisfy allocation guards)
__device__ __nv_bfloat16 g_xb[(size_t)M1 * Hv];        // X in bf16        (25 MB)
__device__ __nv_bfloat16 g_wt[(size_t)NQK * Hv];       // W^T bf16, K-major (2.5 MB)
__device__ __nv_bfloat16 g_qkb[(size_t)M1 * NQK];      // RoPE'd q|k bf16  (54 MB)
__device__ float g_sin[Sv * Dv];
__device__ float g_cos[Sv * Dv];

#define SWZ(x) ((x) ^ (((x) >> 3) & 0x70))
#define STAGES 3
#define GEMM1_SMEM (STAGES * 32768)     /* 96 KB: 3 x (A 16K + B 16K) */

static __device__ __forceinline__ uint32_t smem_u32(const void* p) {
    return (uint32_t)__cvta_generic_to_shared(p);
}

#define CP16(dst, src) \
    asm volatile("cp.async.cg.shared.global [%0], [%1], 16;" :: "r"(dst), "l"(src))
#define CP_COMMIT() asm volatile("cp.async.commit_group;" ::: "memory")
#define CP_WAIT(n)  asm volatile("cp.async.wait_group %0;" :: "n"(n) : "memory")

static __device__ __forceinline__ void ldsm4(uint32_t& r0, uint32_t& r1,
                                             uint32_t& r2, uint32_t& r3, uint32_t addr) {
    asm volatile("ldmatrix.sync.aligned.m8n8.x4.shared.b16 {%0,%1,%2,%3}, [%4];"
                 : "=r"(r0), "=r"(r1), "=r"(r2), "=r"(r3) : "r"(addr));
}
static __device__ __forceinline__ void mma_bf16(float* d, const uint32_t* a,
                                                const uint32_t* b) {
    asm volatile(
        "mma.sync.aligned.m16n8k16.row.col.f32.bf16.bf16.f32 "
        "{%0,%1,%2,%3}, {%4,%5,%6,%7}, {%8,%9}, {%0,%1,%2,%3};"
        : "+f"(d[0]), "+f"(d[1]), "+f"(d[2]), "+f"(d[3])
        : "r"(a[0]), "r"(a[1]), "r"(a[2]), "r"(a[3]), "r"(b[0]), "r"(b[1]));
}

// ---------------------------------------------------------------------------
__global__ void rope_init_kernel() {
    int idx = blockIdx.x * blockDim.x + threadIdx.x;
    if (idx >= Sv * Dv) return;
    int s = idx / Dv, d = idx % Dv, i = d >> 1;
    float inv = powf(10000.0f, -2.0f * (float)i / (float)Dv);
    float ang = (float)s * inv;
    g_sin[idx] = sinf(ang);
    g_cos[idx] = cosf(ang);
}

__global__ __launch_bounds__(256) void conv_x_kernel(const float* __restrict__ X) {
    int i = blockIdx.x * blockDim.x + threadIdx.x;   // one float4 per thread, exact grid
    float4 v = ((const float4*)X)[i];
    __nv_bfloat162 p0 = __floats2bfloat162_rn(v.x, v.y);
    __nv_bfloat162 p1 = __floats2bfloat162_rn(v.z, v.w);
    uint2 u;
    u.x = *(uint32_t*)&p0;
    u.y = *(uint32_t*)&p1;
    *(uint2*)(g_xb + (size_t)i * 4) = u;
}

__global__ void conv_w_kernel(const float* __restrict__ W) {
    __shared__ float s[32][33];
    int nb = blockIdx.x * 32, kb = blockIdx.y * 32;
    int tx = threadIdx.x, ty = threadIdx.y;
    s[ty][tx] = W[(size_t)(kb + ty) * NQK + nb + tx];
    __syncthreads();
    g_wt[(size_t)(nb + ty) * Hv + kb + tx] = __float2bfloat16(s[tx][ty]);
}

// ---------------------------------------------------------------------------
// GEMM1: C[16384,1664] = X @ W + b, RoPE epilogue -> g_qkb (bf16).
// 128x128 CTA tile, 128 threads, 4 warps in 2x2, 64x64 warp tile
// (ldsm:mma = 0.25 vs 0.375 before). K-chunk 64 (SW128), 3-stage cp.async.
// Dynamic smem 96 KB; launch_bounds(128,2) -> 2 CTAs/SM.
// ---------------------------------------------------------------------------
__global__ __launch_bounds__(128, 2) void gemm1_mma(const float* __restrict__ bias) {
    extern __shared__ __align__(1024) uint8_t dynsm[];
    const uint32_t sAb = smem_u32(dynsm);            // A stages: 0,16K,32K
    const uint32_t sBb = sAb + STAGES * 16384;       // B stages: +0,16K,32K

    const int tid = threadIdx.x;
    const int wid = tid >> 5;
    const int lane = tid & 31;
    const int head = blockIdx.x;
    const int rowbase = blockIdx.y * 128;

    const int warp_m = wid & 1;        // 0/1 -> m offset 0/64
    const int warp_n = wid >> 1;       // 0/1 -> n offset 0/64

    // loader: 128 threads, 8 rows each, 16B per row per operand
    const int r0 = tid >> 3, seg = tid & 7;          // r0: 0..15
    const __nv_bfloat16* Abase = g_xb + (size_t)rowbase * Hv + seg * 8;
    const __nv_bfloat16* Bbase = g_wt + (size_t)(head * 128) * Hv + seg * 8;
    uint32_t loff[8];
    #pragma unroll
    for (int t = 0; t < 8; ++t)
        loff[t] = SWZ((r0 + 16 * t) * 128 + seg * 16);

    float acc[4][8][4];
    #pragma unroll
    for (int i = 0; i < 4; ++i)
        #pragma unroll
        for (int j = 0; j < 8; ++j)
            #pragma unroll
            for (int q = 0; q < 4; ++q) acc[i][j][q] = 0.f;

    // prefetch stages 0 and 1
    #pragma unroll
    for (int s = 0; s < 2; ++s) {
        const int k0 = s * 64;
        const uint32_t aDst = sAb + s * 16384;
        const uint32_t bDst = sBb + s * 16384;
        #pragma unroll
        for (int t = 0; t < 8; ++t) {
            CP16(aDst + loff[t], Abase + (size_t)(r0 + 16 * t) * Hv + k0);
            CP16(bDst + loff[t], Bbase + (size_t)(r0 + 16 * t) * Hv + k0);
        }
        CP_COMMIT();
    }

    const int lrow = lane & 15;                 // ldmatrix row within 16-block
    const int lcol16 = (lane >> 4) * 16;        // 0 / 16 bytes (k0 / k8)

    for (int c = 0; c < 12; ++c) {
        CP_WAIT(1);                 // stage c arrived
        __syncthreads();            // buffer (c+2)%3 free for refill

        if (c + 2 < 12) {
            const int k0 = (c + 2) * 64;
            const int sl = (c + 2) % STAGES;
            const uint32_t aDst = sAb + sl * 16384;
            const uint32_t bDst = sBb + sl * 16384;
            #pragma unroll
            for (int t = 0; t < 8; ++t) {
                CP16(aDst + loff[t], Abase + (size_t)(r0 + 16 * t) * Hv + k0);
                CP16(bDst + loff[t], Bbase + (size_t)(r0 + 16 * t) * Hv + k0);
            }
            CP_COMMIT();
        }

        const int sl = c % STAGES;
        const uint32_t aBase = sAb + sl * 16384;
        const uint32_t bBase = sBb + sl * 16384;
        #pragma unroll
        for (int ks = 0; ks < 4; ++ks) {
            const int kbyte = ks * 32 + lcol16;
            uint32_t bfr[8][2];
            #pragma unroll
            for (int nf2 = 0; nf2 < 4; ++nf2) {
                const int rowB = warp_n * 64 + nf2 * 16 + lrow;
                uint32_t b0, b1, b2, b3;
                ldsm4(b0, b1, b2, b3, bBase + SWZ(rowB * 128 + kbyte));
                bfr[2 * nf2][0] = b0; bfr[2 * nf2][1] = b2;
                bfr[2 * nf2 + 1][0] = b1; bfr[2 * nf2 + 1][1] = b3;
            }
            #pragma unroll
            for (int mf = 0; mf < 4; ++mf) {
                const int rowA = warp_m * 64 + mf * 16 + lrow;
                uint32_t a[4];
                ldsm4(a[0], a[1], a[2], a[3], aBase + SWZ(rowA * 128 + kbyte));
                #pragma unroll
                for (int nf = 0; nf < 8; ++nf)
                    mma_bf16(acc[mf][nf], a, bfr[nf]);
            }
        }
        // next iteration's CP_WAIT+sync protects buffer reuse
    }

    // ---- epilogue: bias + RoPE -> bf16 ----
    const int gid = lane >> 2, tig = lane & 3;
    float b0v[8], b1v[8];
    #pragma unroll
    for (int nf = 0; nf < 8; ++nf) {
        const int cl = warp_n * 64 + nf * 8 + tig * 2;
        b0v[nf] = bias[head * 128 + cl];
        b1v[nf] = bias[head * 128 + cl + 1];
    }
    #pragma unroll
    for (int mf = 0; mf < 4; ++mf) {
        #pragma unroll
        for (int h = 0; h < 2; ++h) {
            const int row_l = warp_m * 64 + mf * 16 + gid + 8 * h;
            const int m = rowbase + row_l;
            const int s = m & (Sv - 1);
            #pragma unroll
            for (int nf = 0; nf < 8; ++nf) {
                const int col_l = warp_n * 64 + nf * 8 + tig * 2;
                const int d = col_l & 63;
                float v0 = acc[mf][nf][h * 2]     + b0v[nf];
                float v1 = acc[mf][nf][h * 2 + 1] + b1v[nf];
                float cs = g_cos[s * Dv + d];
                float sn = g_sin[s * Dv + d];
                float o0 = v0 * cs - v1 * sn;
                float o1 = v1 * cs + v0 * sn;
                __nv_bfloat162 p = __floats2bfloat162_rn(o0, o1);
                *(uint32_t*)(g_qkb + (size_t)m * NQK + head * 128 + col_l) =
                    *(uint32_t*)&p;
            }
        }
    }
}

// ---------------------------------------------------------------------------
// GEMM2: per (b,h) logits = q.k^T, fused mask epilogue (fp32).
// Grid (2,2,832). 128x128 tile, single K=64 stage. 32KB static smem.
// ---------------------------------------------------------------------------
__global__ __launch_bounds__(256) void attn_mma(const float* __restrict__ mask,
                                                float* __restrict__ out) {
    __shared__ __align__(1024) uint8_t sQ[16384];
    __shared__ __align__(1024) uint8_t sK[16384];

    const int tid = threadIdx.x;
    const int wid = tid >> 5;
    const int lane = tid & 31;
    const int nt = blockIdx.x, mt = blockIdx.y, bh = blockIdx.z;
    const int b = bh / Tv, h = bh - b * Tv;

    const int warp_m = wid & 1;
    const int warp_n = wid >> 1;

    const uint32_t sQb = smem_u32(sQ);
    const uint32_t sKb = smem_u32(sK);

    const int r0 = tid >> 3, seg = tid & 7;
    const __nv_bfloat16* Qg = g_qkb + (size_t)(b * Sv + mt * 128) * NQK + h * 128 + seg * 8;
    const __nv_bfloat16* Kg = g_qkb + (size_t)(b * Sv + nt * 128) * NQK + h * 128 + 64 + seg * 8;
    #pragma unroll
    for (int t = 0; t < 4; ++t) {
        const int row = r0 + t * 32;
        const uint32_t off = SWZ(row * 128 + seg * 16);
        CP16(sQb + off, Qg + (size_t)row * NQK);
        CP16(sKb + off, Kg + (size_t)row * NQK);
    }
    CP_COMMIT();
    CP_WAIT(0);
    __syncthreads();

    float acc[4][4][4];
    #pragma unroll
    for (int i = 0; i < 4; ++i)
        #pragma unroll
        for (int j = 0; j < 4; ++j)
            #pragma unroll
            for (int q = 0; q < 4; ++q) acc[i][j][q] = 0.f;

    const int lrow = lane & 15;
    const int lcol16 = (lane >> 4) * 16;
    #pragma unroll
    for (int ks = 0; ks < 4; ++ks) {
        const int kbyte = ks * 32 + lcol16;
        uint32_t bfr[4][2];
        #pragma unroll
        for (int nf2 = 0; nf2 < 2; ++nf2) {
            const int rowB = warp_n * 32 + nf2 * 16 + lrow;
            uint32_t b0, b1, b2, b3;
            ldsm4(b0, b1, b2, b3, sKb + SWZ(rowB * 128 + kbyte));
            bfr[2 * nf2][0] = b0; bfr[2 * nf2][1] = b2;
            bfr[2 * nf2 + 1][0] = b1; bfr[2 * nf2 + 1][1] = b3;
        }
        #pragma unroll
        for (int mf = 0; mf < 4; ++mf) {
            const int rowA = warp_m * 64 + mf * 16 + lrow;
            uint32_t a[4];
            ldsm4(a[0], a[1], a[2], a[3], sQb + SWZ(rowA * 128 + kbyte));
            #pragma unroll
            for (int nf = 0; nf < 4; ++nf)
                mma_bf16(acc[mf][nf], a, bfr[nf]);
        }
    }

    // ---- epilogue: pad mask, causal, scale, matching ref op order ----
    const int gid = lane >> 2, tig = lane & 3;
    float pad0[4], pad1[4];
    int ncol[4];
    #pragma unroll
    for (int nf = 0; nf < 4; ++nf) {
        const int n = nt * 128 + warp_n * 32 + nf * 8 + tig * 2;
        ncol[nf] = n;
        pad0[nf] = mask[b * Sv + n];
        pad1[nf] = mask[b * Sv + n + 1];
    }
    #pragma unroll
    for (int mf = 0; mf < 4; ++mf) {
        #pragma unroll
        for (int h = 0; h < 2; ++h) {
            const int m = mt * 128 + warp_m * 64 + mf * 16 + gid + 8 * h;
            float* orow = out + ((size_t)bh * Sv + m) * Sv;
            #pragma unroll
            for (int nf = 0; nf < 4; ++nf) {
                const int n = ncol[nf];
                float t0 = acc[mf][nf][h * 2]     * pad0[nf] - (1.0f - pad0[nf]) * NEGC;
                float t1 = acc[mf][nf][h * 2 + 1] * pad1[nf] - (1.0f - pad1[nf]) * NEGC;
                if (n < m)     t0 -= NEGC;
                if (n + 1 < m) t1 -= NEGC;
                float2 o = make_float2(t0 * 0.125f, t1 * 0.125f);
                *(float2*)(orow + n) = o;
            }
        }
    }
}

// ---------------------------------------------------------------------------
extern "C" void kernel_launch(void* const* d_in, const int* in_sizes, int n_in,
                              void* d_out, int out_size) {
    const float* X    = (const float*)d_in[0];   // (64,256,768)
    const float* W    = (const float*)d_in[1];   // (768,1664)
    const float* bias = (const float*)d_in[2];   // (1664,)
    const float* mask = (const float*)d_in[3];   // (64,256)
    float* out = (float*)d_out;                  // (64,13,256,256)

    cudaFuncSetAttribute(gemm1_mma,
                         cudaFuncAttributeMaxDynamicSharedMemorySize, GEMM1_SMEM);

    rope_init_kernel<<<(Sv * Dv + 255) / 256, 256>>>();
    conv_x_kernel<<<(M1 * Hv / 4) / 256, 256>>>(X);
    conv_w_kernel<<<dim3(NQK / 32, Hv / 32), dim3(32, 32)>>>(W);
    gemm1_mma<<<dim3(Tv, M1 / 128), 128, GEMM1_SMEM>>>(bias);
    attn_mma<<<dim3(2, 2, Bv * Tv), 256>>>(mask, out);
}

// round 8
// speedup vs baseline: 1.1917x; 1.1917x over previous
#include <cuda_runtime.h>
#include <cuda_bf16.h>
#include <cuda_fp16.h>
#include <cstdint>

#define Bv 64
#define Sv 256
#define Hv 768
#define Tv 13
#define Dv 64
#define NQK 1664          /* T*2*D */
#define M1 16384          /* B*S */
#define NEGC 1000000000000.0f

// Scratch (static __device__ to satisfy allocation guards)
__device__ __half g_xh[(size_t)M1 * Hv];               // X in f16         (25 MB)
__device__ __half g_wh[(size_t)NQK * Hv];              // W^T f16, K-major (2.5 MB)
__device__ __nv_bfloat16 g_qkb[(size_t)M1 * NQK];      // RoPE'd q|k bf16  (54 MB)
__device__ float g_sin[Sv * Dv];
__device__ float g_cos[Sv * Dv];

#define SWZ(x) ((x) ^ (((x) >> 3) & 0x70))
#define GEMM1_SMEM 98304     /* A: 2 x 32K @0, B: 2 x 16K @64K */

static __device__ __forceinline__ uint32_t smem_u32(const void* p) {
    return (uint32_t)__cvta_generic_to_shared(p);
}

#define CP16(dst, src) \
    asm volatile("cp.async.cg.shared.global [%0], [%1], 16;" :: "r"(dst), "l"(src))
#define CP_COMMIT() asm volatile("cp.async.commit_group;" ::: "memory")
#define CP_WAIT(n)  asm volatile("cp.async.wait_group %0;" :: "n"(n) : "memory")

static __device__ __forceinline__ void ldsm4(uint32_t& r0, uint32_t& r1,
                                             uint32_t& r2, uint32_t& r3, uint32_t addr) {
    asm volatile("ldmatrix.sync.aligned.m8n8.x4.shared.b16 {%0,%1,%2,%3}, [%4];"
                 : "=r"(r0), "=r"(r1), "=r"(r2), "=r"(r3) : "r"(addr));
}
// f16 inputs, f16 accumulator (2 packed regs)
static __device__ __forceinline__ void mma_h16(uint32_t* d, const uint32_t* a,
                                               const uint32_t* b) {
    asm volatile(
        "mma.sync.aligned.m16n8k16.row.col.f16.f16.f16.f16 "
        "{%0,%1}, {%2,%3,%4,%5}, {%6,%7}, {%0,%1};"
        : "+r"(d[0]), "+r"(d[1])
        : "r"(a[0]), "r"(a[1]), "r"(a[2]), "r"(a[3]), "r"(b[0]), "r"(b[1]));
}
// bf16 inputs, f32 accumulator (attn)
static __device__ __forceinline__ void mma_bf16(float* d, const uint32_t* a,
                                                const uint32_t* b) {
    asm volatile(
        "mma.sync.aligned.m16n8k16.row.col.f32.bf16.bf16.f32 "
        "{%0,%1,%2,%3}, {%4,%5,%6,%7}, {%8,%9}, {%0,%1,%2,%3};"
        : "+f"(d[0]), "+f"(d[1]), "+f"(d[2]), "+f"(d[3])
        : "r"(a[0]), "r"(a[1]), "r"(a[2]), "r"(a[3]), "r"(b[0]), "r"(b[1]));
}

// ---------------------------------------------------------------------------
__global__ void rope_init_kernel() {
    int idx = blockIdx.x * blockDim.x + threadIdx.x;
    if (idx >= Sv * Dv) return;
    int s = idx / Dv, d = idx % Dv, i = d >> 1;
    float inv = powf(10000.0f, -2.0f * (float)i / (float)Dv);
    float ang = (float)s * inv;
    g_sin[idx] = sinf(ang);
    g_cos[idx] = cosf(ang);
}

__global__ __launch_bounds__(256) void conv_x_kernel(const float* __restrict__ X) {
    int i = blockIdx.x * blockDim.x + threadIdx.x;   // one float4 per thread
    float4 v = ((const float4*)X)[i];
    __half2 p0 = __floats2half2_rn(v.x, v.y);
    __half2 p1 = __floats2half2_rn(v.z, v.w);
    uint2 u;
    u.x = *(uint32_t*)&p0;
    u.y = *(uint32_t*)&p1;
    *(uint2*)(g_xh + (size_t)i * 4) = u;
}

__global__ void conv_w_kernel(const float* __restrict__ W) {
    __shared__ float s[32][33];
    int nb = blockIdx.x * 32, kb = blockIdx.y * 32;
    int tx = threadIdx.x, ty = threadIdx.y;
    s[ty][tx] = W[(size_t)(kb + ty) * NQK + nb + tx];
    __syncthreads();
    g_wh[(size_t)(nb + ty) * Hv + kb + tx] = __float2half(s[tx][ty]);
}

// ---------------------------------------------------------------------------
// GEMM1: C[16384,1664] = X @ W + b, RoPE epilogue -> g_qkb (bf16).
// CTA tile 256x128 (grid 13 x 64), 8 warps in 4x2, 64x64 warp tile,
// f16 accumulators (64 regs) -> 2 CTAs/SM = 16 warps/SM.
// K-chunk 64 (SW128), 2-stage cp.async. smem 96 KB.
// ---------------------------------------------------------------------------
__global__ __launch_bounds__(256, 2) void gemm1_mma(const float* __restrict__ bias) {
    extern __shared__ __align__(1024) uint8_t dynsm[];
    const uint32_t sAb = smem_u32(dynsm);            // A: stage s @ s*32K
    const uint32_t sBb = sAb + 65536;                // B: stage s @ 64K + s*16K

    const int tid = threadIdx.x;
    const int wid = tid >> 5;
    const int lane = tid & 31;
    const int head = blockIdx.x;
    const int rowbase = blockIdx.y * 256;

    const int warp_m = wid & 3;        // 0..3 -> m offset *64
    const int warp_n = wid >> 2;       // 0/1  -> n offset *64

    // loader: 256 threads; A: 8 rows x 16B, B: 4 rows x 16B
    const int r0 = tid >> 3, seg = tid & 7;          // r0: 0..31
    const __half* Abase = g_xh + (size_t)rowbase * Hv + seg * 8;
    const __half* Bbase = g_wh + (size_t)(head * 128) * Hv + seg * 8;
    uint32_t loffA[8];
    #pragma unroll
    for (int t = 0; t < 8; ++t)
        loffA[t] = SWZ((r0 + 32 * t) * 128 + seg * 16);

    uint32_t acc[4][8][2];             // f16 acc: [mf][nf][row-half], half2 packed
    #pragma unroll
    for (int i = 0; i < 4; ++i)
        #pragma unroll
        for (int j = 0; j < 8; ++j) { acc[i][j][0] = 0u; acc[i][j][1] = 0u; }

    // prefetch stage 0
    {
        #pragma unroll
        for (int t = 0; t < 8; ++t)
            CP16(sAb + loffA[t], Abase + (size_t)(r0 + 32 * t) * Hv);
        #pragma unroll
        for (int t = 0; t < 4; ++t)
            CP16(sBb + loffA[t], Bbase + (size_t)(r0 + 32 * t) * Hv);
        CP_COMMIT();
    }

    const int lrow = lane & 15;                 // ldmatrix row within 16-block
    const int lcol16 = (lane >> 4) * 16;        // 0 / 16 bytes (k0 / k8)

    for (int c = 0; c < 12; ++c) {
        if (c + 1 < 12) {
            const int k0 = (c + 1) * 64;
            const uint32_t aDst = sAb + ((c + 1) & 1) * 32768;
            const uint32_t bDst = sBb + ((c + 1) & 1) * 16384;
            #pragma unroll
            for (int t = 0; t < 8; ++t)
                CP16(aDst + loffA[t], Abase + (size_t)(r0 + 32 * t) * Hv + k0);
            #pragma unroll
            for (int t = 0; t < 4; ++t)
                CP16(bDst + loffA[t], Bbase + (size_t)(r0 + 32 * t) * Hv + k0);
            CP_COMMIT();
            CP_WAIT(1);
        } else {
            CP_WAIT(0);
        }
        __syncthreads();

        const uint32_t aBase = sAb + (c & 1) * 32768;
        const uint32_t bBase = sBb + (c & 1) * 16384;
        #pragma unroll
        for (int ks = 0; ks < 4; ++ks) {
            const int kbyte = ks * 32 + lcol16;
            uint32_t bfr[8][2];
            #pragma unroll
            for (int nf2 = 0; nf2 < 4; ++nf2) {
                const int rowB = warp_n * 64 + nf2 * 16 + lrow;
                uint32_t b0, b1, b2, b3;
                ldsm4(b0, b1, b2, b3, bBase + SWZ(rowB * 128 + kbyte));
                bfr[2 * nf2][0] = b0; bfr[2 * nf2][1] = b2;
                bfr[2 * nf2 + 1][0] = b1; bfr[2 * nf2 + 1][1] = b3;
            }
            #pragma unroll
            for (int mf = 0; mf < 4; ++mf) {
                const int rowA = warp_m * 64 + mf * 16 + lrow;
                uint32_t a[4];
                ldsm4(a[0], a[1], a[2], a[3], aBase + SWZ(rowA * 128 + kbyte));
                #pragma unroll
                for (int nf = 0; nf < 8; ++nf)
                    mma_h16(acc[mf][nf], a, bfr[nf]);
            }
        }
        __syncthreads();
    }

    // ---- epilogue: bias + RoPE -> bf16 ----
    const int gid = lane >> 2, tig = lane & 3;
    #pragma unroll
    for (int mf = 0; mf < 4; ++mf) {
        #pragma unroll
        for (int h = 0; h < 2; ++h) {
            const int row_l = warp_m * 64 + mf * 16 + gid + 8 * h;
            const int m = rowbase + row_l;
            const int s = m & (Sv - 1);
            #pragma unroll
            for (int nf = 0; nf < 8; ++nf) {
                const int col_l = warp_n * 64 + nf * 8 + tig * 2;
                const int d = col_l & 63;
                __half2 hv = *(__half2*)&acc[mf][nf][h];
                float v0 = __low2float(hv)  + bias[head * 128 + col_l];
                float v1 = __high2float(hv) + bias[head * 128 + col_l + 1];
                float cs = g_cos[s * Dv + d];
                float sn = g_sin[s * Dv + d];
                float o0 = v0 * cs - v1 * sn;
                float o1 = v1 * cs + v0 * sn;
                __nv_bfloat162 p = __floats2bfloat162_rn(o0, o1);
                *(uint32_t*)(g_qkb + (size_t)m * NQK + head * 128 + col_l) =
                    *(uint32_t*)&p;
            }
        }
    }
}

// ---------------------------------------------------------------------------
// GEMM2: per (b,h) logits = q.k^T, fused mask epilogue (fp32).
// Grid (2,2,832). 128x128 tile, single K=64 stage. 32KB static smem.
// ---------------------------------------------------------------------------
__global__ __launch_bounds__(256) void attn_mma(const float* __restrict__ mask,
                                                float* __restrict__ out) {
    __shared__ __align__(1024) uint8_t sQ[16384];
    __shared__ __align__(1024) uint8_t sK[16384];

    const int tid = threadIdx.x;
    const int wid = tid >> 5;
    const int lane = tid & 31;
    const int nt = blockIdx.x, mt = blockIdx.y, bh = blockIdx.z;
    const int b = bh / Tv, h = bh - b * Tv;

    const int warp_m = wid & 1;
    const int warp_n = wid >> 1;

    const uint32_t sQb = smem_u32(sQ);
    const uint32_t sKb = smem_u32(sK);

    const int r0 = tid >> 3, seg = tid & 7;
    const __nv_bfloat16* Qg = g_qkb + (size_t)(b * Sv + mt * 128) * NQK + h * 128 + seg * 8;
    const __nv_bfloat16* Kg = g_qkb + (size_t)(b * Sv + nt * 128) * NQK + h * 128 + 64 + seg * 8;
    #pragma unroll
    for (int t = 0; t < 4; ++t) {
        const int row = r0 + t * 32;
        const uint32_t off = SWZ(row * 128 + seg * 16);
        CP16(sQb + off, Qg + (size_t)row * NQK);
        CP16(sKb + off, Kg + (size_t)row * NQK);
    }
    CP_COMMIT();
    CP_WAIT(0);
    __syncthreads();

    float acc[4][4][4];
    #pragma unroll
    for (int i = 0; i < 4; ++i)
        #pragma unroll
        for (int j = 0; j < 4; ++j)
            #pragma unroll
            for (int q = 0; q < 4; ++q) acc[i][j][q] = 0.f;

    const int lrow = lane & 15;
    const int lcol16 = (lane >> 4) * 16;
    #pragma unroll
    for (int ks = 0; ks < 4; ++ks) {
        const int kbyte = ks * 32 + lcol16;
        uint32_t bfr[4][2];
        #pragma unroll
        for (int nf2 = 0; nf2 < 2; ++nf2) {
            const int rowB = warp_n * 32 + nf2 * 16 + lrow;
            uint32_t b0, b1, b2, b3;
            ldsm4(b0, b1, b2, b3, sKb + SWZ(rowB * 128 + kbyte));
            bfr[2 * nf2][0] = b0; bfr[2 * nf2][1] = b2;
            bfr[2 * nf2 + 1][0] = b1; bfr[2 * nf2 + 1][1] = b3;
        }
        #pragma unroll
        for (int mf = 0; mf < 4; ++mf) {
            const int rowA = warp_m * 64 + mf * 16 + lrow;
            uint32_t a[4];
            ldsm4(a[0], a[1], a[2], a[3], sQb + SWZ(rowA * 128 + kbyte));
            #pragma unroll
            for (int nf = 0; nf < 4; ++nf)
                mma_bf16(acc[mf][nf], a, bfr[nf]);
        }
    }

    // ---- epilogue: pad mask, causal, scale, matching ref op order ----
    const int gid = lane >> 2, tig = lane & 3;
    float pad0[4], pad1[4];
    int ncol[4];
    #pragma unroll
    for (int nf = 0; nf < 4; ++nf) {
        const int n = nt * 128 + warp_n * 32 + nf * 8 + tig * 2;
        ncol[nf] = n;
        pad0[nf] = mask[b * Sv + n];
        pad1[nf] = mask[b * Sv + n + 1];
    }
    #pragma unroll
    for (int mf = 0; mf < 4; ++mf) {
        #pragma unroll
        for (int h = 0; h < 2; ++h) {
            const int m = mt * 128 + warp_m * 64 + mf * 16 + gid + 8 * h;
            float* orow = out + ((size_t)bh * Sv + m) * Sv;
            #pragma unroll
            for (int nf = 0; nf < 4; ++nf) {
                const int n = ncol[nf];
                float t0 = acc[mf][nf][h * 2]     * pad0[nf] - (1.0f - pad0[nf]) * NEGC;
                float t1 = acc[mf][nf][h * 2 + 1] * pad1[nf] - (1.0f - pad1[nf]) * NEGC;
                if (n < m)     t0 -= NEGC;
                if (n + 1 < m) t1 -= NEGC;
                float2 o = make_float2(t0 * 0.125f, t1 * 0.125f);
                *(float2*)(orow + n) = o;
            }
        }
    }
}

// ---------------------------------------------------------------------------
extern "C" void kernel_launch(void* const* d_in, const int* in_sizes, int n_in,
                              void* d_out, int out_size) {
    const float* X    = (const float*)d_in[0];   // (64,256,768)
    const float* W    = (const float*)d_in[1];   // (768,1664)
    const float* bias = (const float*)d_in[2];   // (1664,)
    const float* mask = (const float*)d_in[3];   // (64,256)
    float* out = (float*)d_out;                  // (64,13,256,256)

    cudaFuncSetAttribute(gemm1_mma,
                         cudaFuncAttributeMaxDynamicSharedMemorySize, GEMM1_SMEM);

    rope_init_kernel<<<(Sv * Dv + 255) / 256, 256>>>();
    conv_x_kernel<<<(M1 * Hv / 4) / 256, 256>>>(X);
    conv_w_kernel<<<dim3(NQK / 32, Hv / 32), dim3(32, 32)>>>(W);
    gemm1_mma<<<dim3(Tv, M1 / 256), 256, GEMM1_SMEM>>>(bias);
    attn_mma<<<dim3(2, 2, Bv * Tv), 256>>>(mask, out);
}